// round 16
// baseline (speedup 1.0000x reference)
#include <cuda_runtime.h>

// LDPC BP, (7,4) Hamming, 5 iters, B=262144.
// R16 = R7 math (46-tanh f32, T-formation — fastest family) with:
//   - coalesced smem-staged float4 LOAD (fast ramp, one barrier)
//   - DIRECT scalar register->global stores (no 2nd barrier, no smem
//     round-trip: stores are fire-and-forget, so scatter is tail-cheap)
// Launch shape: TPB=256, grid=1024 (best measured).

__device__ __forceinline__ float tanhf32(float x) {
    float y;
    asm("tanh.approx.f32 %0, %1;" : "=f"(y) : "f"(x));
    return y;
}

#define TPB 256
#define FLOATS_PER_BLK (TPB * 7)          // 1792 floats
#define VEC4_PER_BLK   (FLOATS_PER_BLK/4) // 448

__global__ __launch_bounds__(TPB)
void ldpc_bp_kernel(const float4* __restrict__ llr4, float* __restrict__ out) {
    __shared__ float s[FLOATS_PER_BLK];
    int tid = threadIdx.x;

    // ---- coalesced bulk load: 448 float4 per block ----
    {
        const float4* src = llr4 + (size_t)blockIdx.x * VEC4_PER_BLK;
        float4* s4 = reinterpret_cast<float4*>(s);
#pragma unroll
        for (int i = tid; i < VEC4_PER_BLK; i += TPB)
            s4[i] = src[i];
    }
    __syncthreads();

    // stride-7 smem read (7 coprime 32 -> conflict-free)
    const float* p = s + tid * 7;
    float l0 = p[0], l1 = p[1], l2 = p[2], l3 = p[3], l4 = p[4], l5 = p[5], l6 = p[6];

    // deg-1 constants (valid iters >= 2), halved
    float c0h = 0.5f * tanhf32(l0 + 1.0f);
    float c1h = 0.5f * tanhf32(l1 + 1.0f);
    float c3h = 0.5f * tanhf32(l3 + 1.0f);

    const float base2 = l2 + 0.5f;
    const float base4 = l4 + 0.5f;
    const float base5 = l5 + 0.5f;
    const float base6 = l6;

    float T2, T4, T5, T6;
    float m01, m02, m03;   // row0 -> v2,v4,v6 (half messages)
    float m11, m12, m13;   // row1 -> v2,v5,v6
    float m21, m22, m23;   // row2 -> v4,v5,v6

    // ---------- iteration 1: args = l_v/2, shared per variable ----------
    {
        float tv0 = tanhf32(0.5f * l0);
        float tv1 = tanhf32(0.5f * l1);
        float tv2 = tanhf32(0.5f * l2);
        float tv3 = tanhf32(0.5f * l3);
        float tv4 = tanhf32(0.5f * l4);
        float tv5 = tanhf32(0.5f * l5);
        float tv6 = tanhf32(0.5f * l6);

        float t0h = 0.5f * tv0, t1h = 0.5f * tv1, t3h = 0.5f * tv3;
        float pb0 = tv4 * tv6, pa0 = t0h * tv2;
        m01 = t0h * pb0;  m02 = pa0 * tv6;  m03 = pa0 * tv4;
        float pb1 = tv5 * tv6, pa1 = t1h * tv2;
        m11 = t1h * pb1;  m12 = pa1 * tv6;  m13 = pa1 * tv5;
        float pb2 = tv5 * tv6, pa2 = t3h * tv4;
        m21 = t3h * pb2;  m22 = pa2 * tv6;  m23 = pa2 * tv5;

        T2 = base2 + (m01 + m11);
        T4 = base4 + (m02 + m21);
        T5 = base5 + (m12 + m22);
        T6 = base6 + ((m03 + m13) + m23);
    }

    // ---------- iterations 2..4 ----------
#pragma unroll
    for (int it = 0; it < 3; ++it) {
        float t01 = tanhf32(T2 - m01), t02 = tanhf32(T4 - m02), t03 = tanhf32(T6 - m03);
        float t11 = tanhf32(T2 - m11), t12 = tanhf32(T5 - m12), t13 = tanhf32(T6 - m13);
        float t21 = tanhf32(T4 - m21), t22 = tanhf32(T5 - m22), t23 = tanhf32(T6 - m23);

        float pb0 = t02 * t03, pa0 = c0h * t01;
        m01 = c0h * pb0;  m02 = pa0 * t03;  m03 = pa0 * t02;
        float pb1 = t12 * t13, pa1 = c1h * t11;
        m11 = c1h * pb1;  m12 = pa1 * t13;  m13 = pa1 * t12;
        float pb2 = t22 * t23, pa2 = c3h * t21;
        m21 = c3h * pb2;  m22 = pa2 * t23;  m23 = pa2 * t22;

        T2 = base2 + (m01 + m11);
        T4 = base4 + (m02 + m21);
        T5 = base5 + (m12 + m22);
        T6 = base6 + ((m03 + m13) + m23);
    }

    // ---------- iteration 5 (also deg-1 messages for outputs) ----------
    float m00, m10, m20;
    {
        float t01 = tanhf32(T2 - m01), t02 = tanhf32(T4 - m02), t03 = tanhf32(T6 - m03);
        float t11 = tanhf32(T2 - m11), t12 = tanhf32(T5 - m12), t13 = tanhf32(T6 - m13);
        float t21 = tanhf32(T4 - m21), t22 = tanhf32(T5 - m22), t23 = tanhf32(T6 - m23);

        float pb0 = t02 * t03, pa0 = c0h * t01;
        m01 = c0h * pb0;  m02 = pa0 * t03;  m03 = pa0 * t02;
        m00 = t01 * (0.5f * pb0);
        float pb1 = t12 * t13, pa1 = c1h * t11;
        m11 = c1h * pb1;  m12 = pa1 * t13;  m13 = pa1 * t12;
        m10 = t11 * (0.5f * pb1);
        float pb2 = t22 * t23, pa2 = c3h * t21;
        m21 = c3h * pb2;  m22 = pa2 * t23;  m23 = pa2 * t22;
        m20 = t21 * (0.5f * pb2);

        T2 = base2 + (m01 + m11);
        T4 = base4 + (m02 + m21);
        T5 = base5 + (m12 + m22);
        T6 = base6 + ((m03 + m13) + m23);
    }

    // ---- direct scalar stores from registers (no barrier, no smem) ----
    size_t b = (size_t)blockIdx.x * TPB + tid;
    float* q = out + b * 7;
    q[0] = 4.0f * ((l0 + 1.0f) + m00);
    q[1] = 4.0f * ((l1 + 1.0f) + m10);
    q[2] = 4.0f * T2;
    q[3] = 4.0f * ((l3 + 1.0f) + m20);
    q[4] = 4.0f * T4;
    q[5] = 4.0f * T5;
    q[6] = 4.0f * T6;
}

extern "C" void kernel_launch(void* const* d_in, const int* in_sizes, int n_in,
                              void* d_out, int out_size) {
    const float4* llr4 = (const float4*)d_in[0];
    float* out = (float*)d_out;
    int B = in_sizes[0] / 7;          // 262144, divisible by 256
    int blocks = B / TPB;             // 1024
    ldpc_bp_kernel<<<blocks, TPB>>>(llr4, out);
}

// round 17
// speedup vs baseline: 1.2704x; 1.2704x over previous
#include <cuda_runtime.h>

// LDPC BP, (7,4) Hamming, 5 iters, B=262144.
// R17 = R7 (best: 46-tanh f32, T-formation, smem-staged float4 I/O,
// TPB=256/grid=1024) with WARP-PRIVATE staging: threads [32w,32w+32) use
// smem floats [224w,224w+224) and global float4 [56w,56w+56) exclusively,
// so both block barriers become __syncwarp(). Warps start computing as soon
// as their OWN loads land; no block-level skew in ramp or drain.

__device__ __forceinline__ float tanhf32(float x) {
    float y;
    asm("tanh.approx.f32 %0, %1;" : "=f"(y) : "f"(x));
    return y;
}

#define TPB 256
#define FLOATS_PER_BLK (TPB * 7)            // 1792
#define VEC4_PER_BLK   (FLOATS_PER_BLK/4)   // 448
#define VEC4_PER_WARP  (VEC4_PER_BLK/8)     // 56

__global__ __launch_bounds__(TPB)
void ldpc_bp_kernel(const float4* __restrict__ llr4, float4* __restrict__ out4) {
    __shared__ float s[FLOATS_PER_BLK];
    int tid  = threadIdx.x;
    int lane = tid & 31;
    int warp = tid >> 5;

    // ---- warp-private coalesced load: 56 float4 per warp ----
    float4* s4w = reinterpret_cast<float4*>(s) + warp * VEC4_PER_WARP;
    {
        const float4* src = llr4 + (size_t)blockIdx.x * VEC4_PER_BLK + warp * VEC4_PER_WARP;
#pragma unroll
        for (int i = lane; i < VEC4_PER_WARP; i += 32)
            s4w[i] = src[i];
    }
    __syncwarp();

    // stride-7 smem read (7 coprime 32 -> conflict-free)
    const float* p = s + tid * 7;
    float l0 = p[0], l1 = p[1], l2 = p[2], l3 = p[3], l4 = p[4], l5 = p[5], l6 = p[6];

    // deg-1 constants (valid iters >= 2), halved
    float c0h = 0.5f * tanhf32(l0 + 1.0f);
    float c1h = 0.5f * tanhf32(l1 + 1.0f);
    float c3h = 0.5f * tanhf32(l3 + 1.0f);

    const float base2 = l2 + 0.5f;
    const float base4 = l4 + 0.5f;
    const float base5 = l5 + 0.5f;
    const float base6 = l6;

    float T2, T4, T5, T6;
    float m01, m02, m03;   // row0 -> v2,v4,v6 (half messages)
    float m11, m12, m13;   // row1 -> v2,v5,v6
    float m21, m22, m23;   // row2 -> v4,v5,v6

    // ---------- iteration 1: args = l_v/2, shared per variable ----------
    {
        float tv0 = tanhf32(0.5f * l0);
        float tv1 = tanhf32(0.5f * l1);
        float tv2 = tanhf32(0.5f * l2);
        float tv3 = tanhf32(0.5f * l3);
        float tv4 = tanhf32(0.5f * l4);
        float tv5 = tanhf32(0.5f * l5);
        float tv6 = tanhf32(0.5f * l6);

        float t0h = 0.5f * tv0, t1h = 0.5f * tv1, t3h = 0.5f * tv3;
        float pb0 = tv4 * tv6, pa0 = t0h * tv2;
        m01 = t0h * pb0;  m02 = pa0 * tv6;  m03 = pa0 * tv4;
        float pb1 = tv5 * tv6, pa1 = t1h * tv2;
        m11 = t1h * pb1;  m12 = pa1 * tv6;  m13 = pa1 * tv5;
        float pb2 = tv5 * tv6, pa2 = t3h * tv4;
        m21 = t3h * pb2;  m22 = pa2 * tv6;  m23 = pa2 * tv5;

        T2 = base2 + (m01 + m11);
        T4 = base4 + (m02 + m21);
        T5 = base5 + (m12 + m22);
        T6 = base6 + ((m03 + m13) + m23);
    }

    // ---------- iterations 2..4 ----------
#pragma unroll
    for (int it = 0; it < 3; ++it) {
        float t01 = tanhf32(T2 - m01), t02 = tanhf32(T4 - m02), t03 = tanhf32(T6 - m03);
        float t11 = tanhf32(T2 - m11), t12 = tanhf32(T5 - m12), t13 = tanhf32(T6 - m13);
        float t21 = tanhf32(T4 - m21), t22 = tanhf32(T5 - m22), t23 = tanhf32(T6 - m23);

        float pb0 = t02 * t03, pa0 = c0h * t01;
        m01 = c0h * pb0;  m02 = pa0 * t03;  m03 = pa0 * t02;
        float pb1 = t12 * t13, pa1 = c1h * t11;
        m11 = c1h * pb1;  m12 = pa1 * t13;  m13 = pa1 * t12;
        float pb2 = t22 * t23, pa2 = c3h * t21;
        m21 = c3h * pb2;  m22 = pa2 * t23;  m23 = pa2 * t22;

        T2 = base2 + (m01 + m11);
        T4 = base4 + (m02 + m21);
        T5 = base5 + (m12 + m22);
        T6 = base6 + ((m03 + m13) + m23);
    }

    // ---------- iteration 5 (also deg-1 messages for outputs) ----------
    float m00, m10, m20;
    {
        float t01 = tanhf32(T2 - m01), t02 = tanhf32(T4 - m02), t03 = tanhf32(T6 - m03);
        float t11 = tanhf32(T2 - m11), t12 = tanhf32(T5 - m12), t13 = tanhf32(T6 - m13);
        float t21 = tanhf32(T4 - m21), t22 = tanhf32(T5 - m22), t23 = tanhf32(T6 - m23);

        float pb0 = t02 * t03, pa0 = c0h * t01;
        m01 = c0h * pb0;  m02 = pa0 * t03;  m03 = pa0 * t02;
        m00 = t01 * (0.5f * pb0);
        float pb1 = t12 * t13, pa1 = c1h * t11;
        m11 = c1h * pb1;  m12 = pa1 * t13;  m13 = pa1 * t12;
        m10 = t11 * (0.5f * pb1);
        float pb2 = t22 * t23, pa2 = c3h * t21;
        m21 = c3h * pb2;  m22 = pa2 * t23;  m23 = pa2 * t22;
        m20 = t21 * (0.5f * pb2);

        T2 = base2 + (m01 + m11);
        T4 = base4 + (m02 + m21);
        T5 = base5 + (m12 + m22);
        T6 = base6 + ((m03 + m13) + m23);
    }

    __syncwarp();   // reuse warp-private region for outputs

    float* q = s + tid * 7;
    q[0] = 4.0f * ((l0 + 1.0f) + m00);
    q[1] = 4.0f * ((l1 + 1.0f) + m10);
    q[2] = 4.0f * T2;
    q[3] = 4.0f * ((l3 + 1.0f) + m20);
    q[4] = 4.0f * T4;
    q[5] = 4.0f * T5;
    q[6] = 4.0f * T6;

    __syncwarp();

    // ---- warp-private coalesced store ----
    {
        float4* dst = out4 + (size_t)blockIdx.x * VEC4_PER_BLK + warp * VEC4_PER_WARP;
#pragma unroll
        for (int i = lane; i < VEC4_PER_WARP; i += 32)
            dst[i] = s4w[i];
    }
}

extern "C" void kernel_launch(void* const* d_in, const int* in_sizes, int n_in,
                              void* d_out, int out_size) {
    const float4* llr4 = (const float4*)d_in[0];
    float4* out4 = (float4*)d_out;
    int B = in_sizes[0] / 7;          // 262144, divisible by 256
    int blocks = B / TPB;             // 1024
    ldpc_bp_kernel<<<blocks, TPB>>>(llr4, out4);
}